// round 13
// baseline (speedup 1.0000x reference)
#include <cuda_runtime.h>
#include <cuda_bf16.h>
#include <cstdint>

// LearnedTaskSpecificLinear via warp-specialized HMMA bf16 split precision.
// out[n,o] = sum_i x[n,i] * W[task_ids[n], i, o],  N=2048, I=O=512, T=64.
//
// Block = (task, 64-col tile), 256 threads: warps 0-3 consume (ldsm+mma),
// warps 4-7 produce (LDG -> bf16 hi/lo split -> swizzled STS). Double-buffered
// bf16 tile sets (A 64x64, B 64x64, hi+lo = 32 KB each), named-barrier
// FULL/EMPTY handshake. acc += Ah*Bh + Ah*Bl + Al*Bh in fp32.

#define NUM_TASKS 64
#define N_ROWS    2048
#define IN_SIZE   512
#define OUT_SIZE  512

#define NT        256
#define PER_THREAD (N_ROWS / NT)     // 8
#define M_TILE    64
#define N_TILE    64
#define K_TILE    64
#define N_STAGES  (IN_SIZE / K_TILE) // 8

// per-buffer tile offsets (all tiles: 128-byte rows = 64 bf16)
#define OFF_A_HI  0
#define OFF_A_LO  8192
#define OFF_B_HI  16384
#define OFF_B_LO  24576
#define BUF_BYTES 32768
#define DYN_SMEM  (2 * BUF_BYTES)    // 64 KB

// named barriers (0 reserved for __syncthreads)
#define BAR_FULL0  1
#define BAR_FULL1  2
#define BAR_EMPTY0 3
#define BAR_EMPTY1 4

typedef unsigned long long ull;

static __device__ __forceinline__ uint32_t swz(uint32_t o) {
    return o ^ ((o >> 3) & 0x70);
}
static __device__ __forceinline__ uint32_t smem_u32(const void* p) {
    uint32_t a;
    asm("{ .reg .u64 t; cvta.to.shared.u64 t, %1; cvt.u32.u64 %0, t; }"
        : "=r"(a) : "l"(p));
    return a;
}
static __device__ __forceinline__ void bar_syncn(int id) {
    asm volatile("bar.sync %0, %1;" :: "r"(id), "r"(NT) : "memory");
}
static __device__ __forceinline__ void bar_arriven(int id) {
    asm volatile("bar.arrive %0, %1;" :: "r"(id), "r"(NT) : "memory");
}
// pack: e0 -> low half, e1 -> high half
static __device__ __forceinline__ uint32_t bfhi(float e0, float e1) {
    uint32_t r;
    asm("cvt.rn.bf16x2.f32 %0, %1, %2;" : "=r"(r) : "f"(e1), "f"(e0));
    return r;
}
static __device__ __forceinline__ uint32_t bflo(float e0, float e1, uint32_t h) {
    float h0 = __uint_as_float(h << 16);
    float h1 = __uint_as_float(h & 0xffff0000u);
    return bfhi(e0 - h0, e1 - h1);
}
static __device__ __forceinline__ void ldsm_x4(uint32_t& r0, uint32_t& r1,
                                               uint32_t& r2, uint32_t& r3,
                                               uint32_t addr) {
    asm volatile("ldmatrix.sync.aligned.m8n8.x4.shared.b16 {%0,%1,%2,%3}, [%4];"
                 : "=r"(r0), "=r"(r1), "=r"(r2), "=r"(r3) : "r"(addr));
}
static __device__ __forceinline__ void mma_bf16(float* d, const uint32_t* a,
                                                uint32_t b0, uint32_t b1) {
    asm volatile(
        "mma.sync.aligned.m16n8k16.row.col.f32.bf16.bf16.f32 "
        "{%0,%1,%2,%3}, {%4,%5,%6,%7}, {%8,%9}, {%0,%1,%2,%3};"
        : "+f"(d[0]), "+f"(d[1]), "+f"(d[2]), "+f"(d[3])
        : "r"(a[0]), "r"(a[1]), "r"(a[2]), "r"(a[3]), "r"(b0), "r"(b1));
}

__global__ __launch_bounds__(NT, 2)
void task_linear_ws_kernel(const float* __restrict__ x,
                           const int* __restrict__ tid32,
                           const float* __restrict__ W,
                           float* __restrict__ out) {
    extern __shared__ __align__(128) char dsm[];
    const int t    = blockIdx.x;
    const int ct   = blockIdx.y;
    const int tid  = threadIdx.x;
    const int lane = tid & 31;
    const int wid  = tid >> 5;
    const bool producer = wid >= 4;

    __shared__ unsigned short rows[N_ROWS];
    __shared__ int warp_sums[NT / 32];
    __shared__ int s_n, s_is64;

    const uint32_t sb = smem_u32(dsm);

    if (tid == 0) s_is64 = 0;
    __syncthreads();

    // dtype detect (int32 vs int64): odd-index words of int64 data are zero.
    {
        int v = 0;
        for (int i = tid; i < 256; i += NT) v |= tid32[2 * i + 1];
        #pragma unroll
        for (int o = 16; o > 0; o >>= 1) v |= __shfl_xor_sync(0xffffffffu, v, o);
        if (lane == 0 && v == 0) s_is64 = 1;
    }
    __syncthreads();
    const int stride = s_is64 ? 2 : 1;

    // Deterministic row list (index order) via prefix scan.
    {
        const int base = tid * PER_THREAD;
        int match = 0;
        #pragma unroll
        for (int j = 0; j < PER_THREAD; j++)
            if (tid32[(base + j) * stride] == t) match |= (1 << j);
        int c = __popc(match);
        int incl = c;
        #pragma unroll
        for (int o = 1; o < 32; o <<= 1) {
            int v = __shfl_up_sync(0xffffffffu, incl, o);
            if (lane >= o) incl += v;
        }
        if (lane == 31) warp_sums[wid] = incl;
        __syncthreads();
        int woff = 0;
        #pragma unroll
        for (int q = 0; q < NT / 32; q++)
            if (q < wid) woff += warp_sums[q];
        int pos = woff + incl - c;
        #pragma unroll
        for (int j = 0; j < PER_THREAD; j++)
            if (match & (1 << j)) rows[pos++] = (unsigned short)(base + j);
        if (tid == NT - 1) s_n = pos;
    }
    __syncthreads();
    const int n = s_n;

    int gs = 0;  // global stage counter (buffer parity), same in both roles

    if (producer) {
        // ---------------- producer warps (4..7), ptid 0..127 ----------------
        const int ptid = tid - 128;
        const int ar = ptid & 63;          // A row
        const int aq = ptid >> 6;          // A k-half (32 k)
        const int bn = ptid & 63;          // B col
        const int bq = ptid >> 6;          // B k-half (32 k)

        for (int m0 = 0; m0 < n; m0 += M_TILE) {
            const bool avalid = (m0 + ar) < n;
            const float* xrow =
                x + (size_t)(avalid ? rows[m0 + ar] : 0) * IN_SIZE;

            for (int st = 0; st < N_STAGES; st++) {
                const int kbase = st * K_TILE;
                const int buf = gs & 1;
                char* tb = dsm + buf * BUF_BYTES;

                if (gs >= 2) bar_syncn(BAR_EMPTY0 + buf);  // wait consumers

                // A: x[m0+ar][kbase + aq*32 .. +32] -> hi/lo
                {
                    const float* xp = xrow + kbase + aq * 32;
                    #pragma unroll
                    for (int j = 0; j < 8; j++) {
                        float4 v = avalid ? *(const float4*)(xp + j * 4)
                                          : make_float4(0.f, 0.f, 0.f, 0.f);
                        uint32_t h0 = bfhi(v.x, v.y), h1 = bfhi(v.z, v.w);
                        uint32_t l0 = bflo(v.x, v.y, h0), l1 = bflo(v.z, v.w, h1);
                        uint32_t off = swz((uint32_t)(ar * 128 + (aq * 32 + j * 4) * 2));
                        *(ull*)(tb + OFF_A_HI + off) = ((ull)h1 << 32) | h0;
                        *(ull*)(tb + OFF_A_LO + off) = ((ull)l1 << 32) | l0;
                    }
                }
                // B: W[k][n] -> smem [n][k] hi/lo (transpose; coalesced LDG)
                {
                    const float* wcol =
                        W + ((size_t)t * IN_SIZE + kbase + bq * 32) * OUT_SIZE
                          + (size_t)ct * N_TILE + bn;
                    #pragma unroll
                    for (int p = 0; p < 16; p++) {
                        float e0 = wcol[(size_t)(2 * p) * OUT_SIZE];
                        float e1 = wcol[(size_t)(2 * p + 1) * OUT_SIZE];
                        uint32_t h = bfhi(e0, e1);
                        uint32_t l = bflo(e0, e1, h);
                        uint32_t off = swz((uint32_t)(bn * 128 + (bq * 32 + 2 * p) * 2));
                        *(uint32_t*)(tb + OFF_B_HI + off) = h;
                        *(uint32_t*)(tb + OFF_B_LO + off) = l;
                    }
                }
                asm volatile("membar.cta;" ::: "memory");  // STS visible
                bar_arriven(BAR_FULL0 + buf);
                gs++;
            }
        }
    } else {
        // ---------------- consumer warps (0..3) ----------------
        const int mw = wid >> 1;   // m-half: rows mw*32..+32
        const int nw = wid & 1;    // n-half: cols nw*32..+32

        for (int m0 = 0; m0 < n; m0 += M_TILE) {
            float acc[2][4][4];
            #pragma unroll
            for (int tm = 0; tm < 2; tm++)
                #pragma unroll
                for (int tn = 0; tn < 4; tn++)
                    #pragma unroll
                    for (int c = 0; c < 4; c++) acc[tm][tn][c] = 0.f;

            for (int st = 0; st < N_STAGES; st++) {
                const int buf = gs & 1;
                const uint32_t tb32 = sb + buf * BUF_BYTES;

                bar_syncn(BAR_FULL0 + buf);   // wait producers

                #pragma unroll
                for (int ks = 0; ks < 4; ks++) {
                    const uint32_t kcol =
                        (uint32_t)((ks * 16 + ((lane >> 4) & 1) * 8) * 2);

                    uint32_t ah[2][4], al[2][4], bh[2][4], bl[2][4];
                    #pragma unroll
                    for (int tm = 0; tm < 2; tm++) {
                        uint32_t off = swz(
                            (uint32_t)((mw * 32 + tm * 16 + (lane & 15)) * 128)
                            + kcol);
                        ldsm_x4(ah[tm][0], ah[tm][1], ah[tm][2], ah[tm][3],
                                tb32 + OFF_A_HI + off);
                        ldsm_x4(al[tm][0], al[tm][1], al[tm][2], al[tm][3],
                                tb32 + OFF_A_LO + off);
                    }
                    #pragma unroll
                    for (int tp = 0; tp < 2; tp++) {
                        uint32_t off = swz(
                            (uint32_t)((nw * 32 + tp * 16 + (lane & 15)) * 128)
                            + kcol);
                        ldsm_x4(bh[tp][0], bh[tp][1], bh[tp][2], bh[tp][3],
                                tb32 + OFF_B_HI + off);
                        ldsm_x4(bl[tp][0], bl[tp][1], bl[tp][2], bl[tp][3],
                                tb32 + OFF_B_LO + off);
                    }
                    #pragma unroll
                    for (int tm = 0; tm < 2; tm++) {
                        #pragma unroll
                        for (int tn = 0; tn < 4; tn++) {
                            const int tp = tn >> 1, sl = tn & 1;
                            mma_bf16(acc[tm][tn], ah[tm], bh[tp][sl], bh[tp][2 + sl]);
                            mma_bf16(acc[tm][tn], ah[tm], bl[tp][sl], bl[tp][2 + sl]);
                            mma_bf16(acc[tm][tn], al[tm], bh[tp][sl], bh[tp][2 + sl]);
                        }
                    }
                }
                bar_arriven(BAR_EMPTY0 + buf);  // reads done (data in regs)
                gs++;
            }

            // epilogue: fragment -> out
            #pragma unroll
            for (int tm = 0; tm < 2; tm++) {
                #pragma unroll
                for (int tn = 0; tn < 4; tn++) {
                    const int col = ct * N_TILE + nw * 32 + tn * 8 + (lane & 3) * 2;
                    int m_lo = m0 + mw * 32 + tm * 16 + (lane >> 2);
                    if (m_lo < n) {
                        float* o = out + (size_t)rows[m_lo] * OUT_SIZE + col;
                        o[0] = acc[tm][tn][0];
                        o[1] = acc[tm][tn][1];
                    }
                    int m_hi = m_lo + 8;
                    if (m_hi < n) {
                        float* o = out + (size_t)rows[m_hi] * OUT_SIZE + col;
                        o[0] = acc[tm][tn][2];
                        o[1] = acc[tm][tn][3];
                    }
                }
            }
        }
    }
}

extern "C" void kernel_launch(void* const* d_in, const int* in_sizes, int n_in,
                              void* d_out, int out_size) {
    const float* x = nullptr;
    const int*   tids = nullptr;
    const float* W = nullptr;
    for (int i = 0; i < n_in; i++) {
        if (in_sizes[i] == N_ROWS * IN_SIZE)                    x = (const float*)d_in[i];
        else if (in_sizes[i] == N_ROWS)                         tids = (const int*)d_in[i];
        else if (in_sizes[i] == NUM_TASKS * IN_SIZE * OUT_SIZE) W = (const float*)d_in[i];
    }
    float* out = (float*)d_out;

    cudaFuncSetAttribute(task_linear_ws_kernel,
                         cudaFuncAttributeMaxDynamicSharedMemorySize, DYN_SMEM);
    dim3 grid(NUM_TASKS, OUT_SIZE / N_TILE);   // 64 x 8 = 512 blocks
    task_linear_ws_kernel<<<grid, NT, DYN_SMEM>>>(x, tids, W, out);
}

// round 14
// speedup vs baseline: 1.1820x; 1.1820x over previous
#include <cuda_runtime.h>
#include <cuda_bf16.h>
#include <cstdint>

// LearnedTaskSpecificLinear via mma.sync (HMMA) bf16 split precision.
// out[n,o] = sum_i x[n,i] * W[task_ids[n], i, o],  N=2048, I=O=512, T=64.
//
// Block = (task, 128-col tile), 256 threads (8 warps = 2m x 4n).
// M_TILE=64 logical, but all per-m16-tile work (A convert, A ldmatrix, MMA,
// epilogue) is predicated on tile_base < n -- with n~32 per task this skips
// ~half the tensor + A-side work chip-wide. K staged 64 at a time.
// Split: v = hi(bf16) + lo(bf16 residual); acc += Ah*Bh + Ah*Bl + Al*Bh (fp32).

#define NUM_TASKS 64
#define N_ROWS    2048
#define IN_SIZE   512
#define OUT_SIZE  512

#define NT        256
#define PER_THREAD (N_ROWS / NT)     // 8
#define M_TILE    64
#define N_TILE    128
#define K_TILE    64
#define N_STAGES  (IN_SIZE / K_TILE) // 8

// dynamic smem layout (all tiles have 128-byte rows: 64 bf16)
#define OFF_A_HI  0
#define OFF_A_LO  (OFF_A_HI + M_TILE * 128)     //  8192
#define OFF_B_HI  (OFF_A_LO + M_TILE * 128)     // 16384
#define OFF_B_LO  (OFF_B_HI + N_TILE * 128)     // 32768
#define DYN_SMEM  (OFF_B_LO + N_TILE * 128)     // 49152

typedef unsigned long long ull;

static __device__ __forceinline__ uint32_t swz(uint32_t o) {
    return o ^ ((o >> 3) & 0x70);
}
static __device__ __forceinline__ uint32_t smem_u32(const void* p) {
    uint32_t a;
    asm("{ .reg .u64 t; cvta.to.shared.u64 t, %1; cvt.u32.u64 %0, t; }"
        : "=r"(a) : "l"(p));
    return a;
}
// pack: e0 -> low half, e1 -> high half
static __device__ __forceinline__ uint32_t bfhi(float e0, float e1) {
    uint32_t r;
    asm("cvt.rn.bf16x2.f32 %0, %1, %2;" : "=r"(r) : "f"(e1), "f"(e0));
    return r;
}
static __device__ __forceinline__ uint32_t bflo(float e0, float e1, uint32_t h) {
    float h0 = __uint_as_float(h << 16);
    float h1 = __uint_as_float(h & 0xffff0000u);
    return bfhi(e0 - h0, e1 - h1);
}
static __device__ __forceinline__ void ldsm_x4(uint32_t& r0, uint32_t& r1,
                                               uint32_t& r2, uint32_t& r3,
                                               uint32_t addr) {
    asm volatile("ldmatrix.sync.aligned.m8n8.x4.shared.b16 {%0,%1,%2,%3}, [%4];"
                 : "=r"(r0), "=r"(r1), "=r"(r2), "=r"(r3) : "r"(addr));
}
static __device__ __forceinline__ void mma_bf16(float* d, const uint32_t* a,
                                                uint32_t b0, uint32_t b1) {
    asm volatile(
        "mma.sync.aligned.m16n8k16.row.col.f32.bf16.bf16.f32 "
        "{%0,%1,%2,%3}, {%4,%5,%6,%7}, {%8,%9}, {%0,%1,%2,%3};"
        : "+f"(d[0]), "+f"(d[1]), "+f"(d[2]), "+f"(d[3])
        : "r"(a[0]), "r"(a[1]), "r"(a[2]), "r"(a[3]), "r"(b0), "r"(b1));
}

__global__ __launch_bounds__(NT)
void task_linear_mma_kernel(const float* __restrict__ x,
                            const int* __restrict__ tid32,
                            const float* __restrict__ W,
                            float* __restrict__ out) {
    extern __shared__ __align__(128) char dsm[];
    const int t    = blockIdx.x;
    const int ct   = blockIdx.y;
    const int tid  = threadIdx.x;
    const int lane = tid & 31;
    const int wid  = tid >> 5;
    const int mw   = wid >> 2;     // warp m-half (0/1): rows mw*32..+32
    const int nw   = wid & 3;      // warp n-quarter: cols nw*32..+32

    __shared__ unsigned short rows[N_ROWS];
    __shared__ int warp_sums[NT / 32];
    __shared__ int s_n, s_is64;

    const uint32_t sb = smem_u32(dsm);

    if (tid == 0) s_is64 = 0;
    __syncthreads();

    // dtype detect (int32 vs int64): odd-index words of int64 data are zero.
    {
        int v = 0;
        for (int i = tid; i < 256; i += NT) v |= tid32[2 * i + 1];
        #pragma unroll
        for (int o = 16; o > 0; o >>= 1) v |= __shfl_xor_sync(0xffffffffu, v, o);
        if (lane == 0 && v == 0) s_is64 = 1;
    }
    __syncthreads();
    const int stride = s_is64 ? 2 : 1;

    // Deterministic row list (index order) via prefix scan.
    {
        const int base = tid * PER_THREAD;
        int match = 0;
        #pragma unroll
        for (int j = 0; j < PER_THREAD; j++)
            if (tid32[(base + j) * stride] == t) match |= (1 << j);
        int c = __popc(match);
        int incl = c;
        #pragma unroll
        for (int o = 1; o < 32; o <<= 1) {
            int v = __shfl_up_sync(0xffffffffu, incl, o);
            if (lane >= o) incl += v;
        }
        if (lane == 31) warp_sums[wid] = incl;
        __syncthreads();
        int woff = 0;
        #pragma unroll
        for (int q = 0; q < NT / 32; q++)
            if (q < wid) woff += warp_sums[q];
        int pos = woff + incl - c;
        #pragma unroll
        for (int j = 0; j < PER_THREAD; j++)
            if (match & (1 << j)) rows[pos++] = (unsigned short)(base + j);
        if (tid == NT - 1) s_n = pos;
    }
    __syncthreads();
    const int n = s_n;
    const int n16 = (n + 15) & ~15;   // rows padded to m16 granularity

    // Conversion thread mappings (constant):
    //   A: row ar = tid&63, k-quarter aq = tid>>6 (16 floats each)
    //   B: col bn = tid&127, k-half bq = tid>>7 (32 k each)
    const int ar = tid & 63;
    const int aq = tid >> 6;
    const int bn = tid & 127;
    const int bq = tid >> 7;

    for (int m0 = 0; m0 < n; m0 += M_TILE) {
        float acc[2][4][4];
        #pragma unroll
        for (int tm = 0; tm < 2; tm++)
            #pragma unroll
            for (int tn = 0; tn < 4; tn++)
                #pragma unroll
                for (int c = 0; c < 4; c++) acc[tm][tn][c] = 0.f;

        // A-side predicates: only rows < padded n are ever read by live tiles.
        const bool aactive = (m0 + ar) < n16;
        const bool avalid  = (m0 + ar) < n;
        const float* xrow = x + (size_t)(avalid ? rows[m0 + ar] : 0) * IN_SIZE;
        // Per-warp m16-tile liveness (warp-uniform; safe around ldmatrix).
        bool tmlive[2];
        #pragma unroll
        for (int tm = 0; tm < 2; tm++)
            tmlive[tm] = (m0 + mw * 32 + tm * 16) < n;
        const bool any_tm = tmlive[0] | tmlive[1];

        for (int st = 0; st < N_STAGES; st++) {
            const int kbase = st * K_TILE;

            // ---- convert A (only for rows any live tile will read) ----
            if (aactive) {
                const float* xp = xrow + kbase + aq * 16;
                #pragma unroll
                for (int j = 0; j < 4; j++) {
                    float4 v = avalid ? *(const float4*)(xp + j * 4)
                                      : make_float4(0.f, 0.f, 0.f, 0.f);
                    uint32_t h0 = bfhi(v.x, v.y), h1 = bfhi(v.z, v.w);
                    uint32_t l0 = bflo(v.x, v.y, h0), l1 = bflo(v.z, v.w, h1);
                    uint32_t off = swz((uint32_t)(ar * 128 + (aq * 16 + j * 4) * 2));
                    *(ull*)(dsm + OFF_A_HI + off) = ((ull)h1 << 32) | h0;
                    *(ull*)(dsm + OFF_A_LO + off) = ((ull)l1 << 32) | l0;
                }
            }
            // ---- convert B: W[k][n] -> smem [n][k] bf16 hi/lo (transpose) ----
            {
                const float* wcol = W + ((size_t)t * IN_SIZE + kbase + bq * 32) * OUT_SIZE
                                      + (size_t)ct * N_TILE + bn;
                #pragma unroll
                for (int p = 0; p < 16; p++) {
                    float e0 = wcol[(size_t)(2 * p) * OUT_SIZE];
                    float e1 = wcol[(size_t)(2 * p + 1) * OUT_SIZE];
                    uint32_t h = bfhi(e0, e1);
                    uint32_t l = bflo(e0, e1, h);
                    uint32_t off = swz((uint32_t)(bn * 128 + (bq * 32 + 2 * p) * 2));
                    *(uint32_t*)(dsm + OFF_B_HI + off) = h;
                    *(uint32_t*)(dsm + OFF_B_LO + off) = l;
                }
            }
            __syncthreads();

            // ---- 4 k16 steps of HMMA (skip dead m16 tiles) ----
            if (any_tm) {
                #pragma unroll
                for (int ks = 0; ks < 4; ks++) {
                    const int k0 = ks * 16;
                    const uint32_t kcol = (uint32_t)((k0 + ((lane >> 4) & 1) * 8) * 2);

                    uint32_t ah[2][4], al[2][4], bh[2][4], bl[2][4];
                    #pragma unroll
                    for (int tm = 0; tm < 2; tm++) {
                        if (!tmlive[tm]) continue;
                        uint32_t off = swz((uint32_t)((mw * 32 + tm * 16 + (lane & 15)) * 128) + kcol);
                        ldsm_x4(ah[tm][0], ah[tm][1], ah[tm][2], ah[tm][3],
                                sb + OFF_A_HI + off);
                        ldsm_x4(al[tm][0], al[tm][1], al[tm][2], al[tm][3],
                                sb + OFF_A_LO + off);
                    }
                    #pragma unroll
                    for (int tp = 0; tp < 2; tp++) {
                        uint32_t off = swz((uint32_t)((nw * 32 + tp * 16 + (lane & 15)) * 128) + kcol);
                        ldsm_x4(bh[tp][0], bh[tp][1], bh[tp][2], bh[tp][3],
                                sb + OFF_B_HI + off);
                        ldsm_x4(bl[tp][0], bl[tp][1], bl[tp][2], bl[tp][3],
                                sb + OFF_B_LO + off);
                    }
                    #pragma unroll
                    for (int tm = 0; tm < 2; tm++) {
                        if (!tmlive[tm]) continue;
                        #pragma unroll
                        for (int tn = 0; tn < 4; tn++) {
                            const int tp = tn >> 1, sl = tn & 1;
                            mma_bf16(acc[tm][tn], ah[tm], bh[tp][sl], bh[tp][2 + sl]);
                            mma_bf16(acc[tm][tn], ah[tm], bl[tp][sl], bl[tp][2 + sl]);
                            mma_bf16(acc[tm][tn], al[tm], bh[tp][sl], bh[tp][2 + sl]);
                        }
                    }
                }
            }
            __syncthreads();   // tiles consumed before next stage overwrites
        }

        // ---- epilogue: D fragments -> out (dead tiles skipped) ----
        #pragma unroll
        for (int tm = 0; tm < 2; tm++) {
            if (!tmlive[tm]) continue;
            #pragma unroll
            for (int tn = 0; tn < 4; tn++) {
                const int col = ct * N_TILE + nw * 32 + tn * 8 + (lane & 3) * 2;
                int m_lo = m0 + mw * 32 + tm * 16 + (lane >> 2);
                if (m_lo < n) {
                    float* o = out + (size_t)rows[m_lo] * OUT_SIZE + col;
                    o[0] = acc[tm][tn][0];
                    o[1] = acc[tm][tn][1];
                }
                int m_hi = m_lo + 8;
                if (m_hi < n) {
                    float* o = out + (size_t)rows[m_hi] * OUT_SIZE + col;
                    o[0] = acc[tm][tn][2];
                    o[1] = acc[tm][tn][3];
                }
            }
        }
        __syncthreads();   // smem reuse safety across m-tiles
    }
}

extern "C" void kernel_launch(void* const* d_in, const int* in_sizes, int n_in,
                              void* d_out, int out_size) {
    const float* x = nullptr;
    const int*   tids = nullptr;
    const float* W = nullptr;
    for (int i = 0; i < n_in; i++) {
        if (in_sizes[i] == N_ROWS * IN_SIZE)                    x = (const float*)d_in[i];
        else if (in_sizes[i] == N_ROWS)                         tids = (const int*)d_in[i];
        else if (in_sizes[i] == NUM_TASKS * IN_SIZE * OUT_SIZE) W = (const float*)d_in[i];
    }
    float* out = (float*)d_out;

    cudaFuncSetAttribute(task_linear_mma_kernel,
                         cudaFuncAttributeMaxDynamicSharedMemorySize, DYN_SMEM);
    dim3 grid(NUM_TASKS, OUT_SIZE / N_TILE);   // 64 x 4 = 256 blocks
    task_linear_mma_kernel<<<grid, NT, DYN_SMEM>>>(x, tids, W, out);
}